// round 1
// baseline (speedup 1.0000x reference)
#include <cuda_runtime.h>
#include <cuda_bf16.h>
#include <mma.h>

using namespace nvcuda;

#define Bb 256
#define Dd 256
#define Tt 512
#define Hh 512
#define G4 2048
#define Mm (Tt*Bb)   // 131072

// ---------------- device scratch (no runtime allocation allowed) ----------------
__device__ __nv_bfloat16 g_xb[(size_t)Mm*Dd];        // xs as bf16, [t*B+b][d]   64 MB
__device__ float         g_xg[(size_t)Mm*G4];        // x_gates fp32            1 GB
__device__ __nv_bfloat16 g_wih[(size_t)Dd*G4];       // W_ih^T bf16 [k][n]
__device__ __nv_bfloat16 g_whh[(size_t)Hh*G4];       // W_hh^T bf16 [k][n]
__device__ float         g_biasmat[16*G4];           // 16 identical rows of (b_ih+b_hh)
__device__ __nv_bfloat16 g_h[2][(size_t)Bb*Hh];      // double-buffered hidden state
__device__ float         g_plog[16*(size_t)Tt*Bb];   // partial logits per u-tile
__device__ unsigned int  g_bar;

__device__ __forceinline__ float sigm(float x) { return 1.0f / (1.0f + __expf(-x)); }

// ---------------- init: zero h0 and barrier ----------------
__global__ void k_init() {
    int i = blockIdx.x * blockDim.x + threadIdx.x;
    if (i == 0) g_bar = 0u;
    if (i < Bb * Hh) g_h[0][i] = __float2bfloat16(0.0f);
}

// ---------------- weight converts (transpose to [k][n], bf16) ----------------
__global__ void k_convert(const float* __restrict__ Wih, const float* __restrict__ Whh,
                          const float* __restrict__ bih, const float* __restrict__ bhh) {
    int i = blockIdx.x * blockDim.x + threadIdx.x;
    if (i < Dd * G4) {
        int k = i / G4, n = i % G4;
        g_wih[i] = __float2bfloat16(Wih[(size_t)n * Dd + k]);
    }
    if (i < Hh * G4) {
        int k = i / G4, n = i % G4;
        g_whh[i] = __float2bfloat16(Whh[(size_t)n * Hh + k]);
    }
    if (i < 16 * G4) {
        int n = i % G4;
        g_biasmat[i] = bih[n] + bhh[n];
    }
}

// ---------------- transpose x (B,D,T) -> g_xb[(t*B+b)*D + d] bf16 ----------------
__global__ void k_transpose(const float* __restrict__ x) {
    __shared__ float tile[32][33];
    int b  = blockIdx.z;
    int d0 = blockIdx.y * 32, t0 = blockIdx.x * 32;
    int tx = threadIdx.x, ty = threadIdx.y;   // 32 x 8
    const float* src = x + ((size_t)b * Dd + d0) * Tt + t0;
    for (int r = ty; r < 32; r += 8)
        tile[r][tx] = src[(size_t)r * Tt + tx];
    __syncthreads();
    for (int r = ty; r < 32; r += 8)
        g_xb[((size_t)(t0 + r) * Bb + b) * Dd + d0 + tx] = __float2bfloat16(tile[tx][r]);
}

// ---------------- GEMM1: g_xg = g_xb (M x 256) @ g_wih (256 x 2048) + bias ----------------
__global__ void k_gemm1() {
    __shared__ __nv_bfloat16 As[64][40];
    __shared__ __nv_bfloat16 Bs[32][72];
    int m0 = blockIdx.x * 64, n0 = blockIdx.y * 64;
    int tid = threadIdx.x;
    int w = tid >> 5;
    int mw = (w >> 1) * 32, nw = (w & 1) * 32;

    wmma::fragment<wmma::accumulator, 16, 16, 16, float> acc[2][2];
    #pragma unroll
    for (int i = 0; i < 2; i++)
        #pragma unroll
        for (int j = 0; j < 2; j++)
            wmma::load_matrix_sync(acc[i][j], &g_biasmat[n0 + nw + 16 * j], G4, wmma::mem_row_major);

    for (int k0 = 0; k0 < Dd; k0 += 32) {
        __syncthreads();
        #pragma unroll
        for (int it = 0; it < 2; it++) {
            int idx = tid + it * 128;
            int r = idx >> 2, c = (idx & 3) * 8;
            *(uint4*)&As[r][c] = *(const uint4*)&g_xb[(size_t)(m0 + r) * Dd + k0 + c];
        }
        #pragma unroll
        for (int it = 0; it < 2; it++) {
            int idx = tid + it * 128;
            int r = idx >> 3, c = (idx & 7) * 8;
            *(uint4*)&Bs[r][c] = *(const uint4*)&g_wih[(size_t)(k0 + r) * G4 + n0 + c];
        }
        __syncthreads();
        #pragma unroll
        for (int kk = 0; kk < 32; kk += 16) {
            wmma::fragment<wmma::matrix_a, 16, 16, 16, __nv_bfloat16, wmma::row_major> af[2];
            wmma::fragment<wmma::matrix_b, 16, 16, 16, __nv_bfloat16, wmma::row_major> bf[2];
            wmma::load_matrix_sync(af[0], &As[mw][kk], 40);
            wmma::load_matrix_sync(af[1], &As[mw + 16][kk], 40);
            wmma::load_matrix_sync(bf[0], &Bs[kk][nw], 72);
            wmma::load_matrix_sync(bf[1], &Bs[kk][nw + 16], 72);
            #pragma unroll
            for (int i = 0; i < 2; i++)
                #pragma unroll
                for (int j = 0; j < 2; j++)
                    wmma::mma_sync(acc[i][j], af[i], bf[j], acc[i][j]);
        }
    }
    #pragma unroll
    for (int i = 0; i < 2; i++)
        #pragma unroll
        for (int j = 0; j < 2; j++)
            wmma::store_matrix_sync(&g_xg[(size_t)(m0 + mw + 16 * i) * G4 + n0 + nw + 16 * j],
                                    acc[i][j], G4, wmma::mem_row_major);
}

// ---------------- persistent LSTM recurrence ----------------
// grid = 128 CTAs: blockIdx = bt*16 + ut ; CTA owns batch rows [bt*32, +32), units [ut*32, +32)
#define BS_LD 136
#define AS_LD 520
#define HT_LD 36
#define DSMEM_BYTES (512*BS_LD*2 + 32*AS_LD*2 + 32*HT_LD*4)

__global__ void __launch_bounds__(128, 1) k_lstm(const float* __restrict__ Wmlp) {
    extern __shared__ char smem[];
    __nv_bfloat16* Bs = (__nv_bfloat16*)smem;                          // [512][BS_LD]
    __nv_bfloat16* As = (__nv_bfloat16*)(smem + 512 * BS_LD * 2);      // [32][AS_LD]
    float*         Ht = (float*)(smem + 512 * BS_LD * 2 + 32 * AS_LD * 2); // [32][HT_LD]
    __shared__ float Wm[32];

    int tid = threadIdx.x, w = tid >> 5;
    int ut = blockIdx.x & 15, bt = blockIdx.x >> 4;
    int u0 = ut * 32, b0 = bt * 32;
    int bh = (w >> 1) * 16, uh = (w & 1) * 16;
    unsigned nCTA = gridDim.x;

    // preload W_hh slice into SMEM: Bs[k][g*32+uu] = W_hh[g*512+u0+uu][k]
    for (int idx = tid; idx < 512 * 16; idx += 128) {
        int k = idx >> 4;
        int col = (idx & 15) * 8;
        int g = col >> 5, uu = col & 31;
        *(uint4*)&Bs[k * BS_LD + col] = *(const uint4*)&g_whh[(size_t)k * G4 + g * 512 + u0 + uu];
    }
    if (tid < 32) Wm[tid] = Wmlp[u0 + tid];

    float c_reg[8];
    #pragma unroll
    for (int e = 0; e < 8; e++) c_reg[e] = 0.0f;

    __syncthreads();

    for (int t = 0; t < Tt; t++) {
        int cur = t & 1, nxt = cur ^ 1;

        // copy my h rows (32 x 512 bf16) from global (L2-coherent) into SMEM
        const __nv_bfloat16* hsrc = g_h[cur] + (size_t)b0 * Hh;
        for (int idx = tid; idx < 32 * 64; idx += 128) {
            int r = idx >> 6, c = (idx & 63) * 8;
            *(uint4*)&As[r * AS_LD + c] = __ldcg((const uint4*)&hsrc[(size_t)r * Hh + c]);
        }
        __syncthreads();

        // accumulators = x_gates tile (fp32, already includes biases)
        wmma::fragment<wmma::accumulator, 16, 16, 16, float> acc[4];
        const float* xgp = g_xg + ((size_t)t * Bb + b0 + bh) * G4 + u0 + uh;
        #pragma unroll
        for (int g = 0; g < 4; g++)
            wmma::load_matrix_sync(acc[g], xgp + g * 512, G4, wmma::mem_row_major);

        // gates += h @ W_hh^T  (K = 512)
        for (int k0 = 0; k0 < 512; k0 += 16) {
            wmma::fragment<wmma::matrix_a, 16, 16, 16, __nv_bfloat16, wmma::row_major> af;
            wmma::load_matrix_sync(af, &As[bh * AS_LD + k0], AS_LD);
            #pragma unroll
            for (int g = 0; g < 4; g++) {
                wmma::fragment<wmma::matrix_b, 16, 16, 16, __nv_bfloat16, wmma::row_major> bf;
                wmma::load_matrix_sync(bf, &Bs[k0 * BS_LD + g * 32 + uh], BS_LD);
                wmma::mma_sync(acc[g], af, bf, acc[g]);
            }
        }

        // elementwise LSTM cell (c stays in registers; all 4 frags share the same layout)
        wmma::fragment<wmma::accumulator, 16, 16, 16, float> hf;
        #pragma unroll
        for (int e = 0; e < 8; e++) {
            float ig = sigm(acc[0].x[e]);
            float fg = sigm(acc[1].x[e]);
            float gg = tanhf(acc[2].x[e]);
            float og = sigm(acc[3].x[e]);
            float cn = fg * c_reg[e] + ig * gg;
            c_reg[e] = cn;
            hf.x[e] = og * tanhf(cn);
        }
        wmma::store_matrix_sync(&Ht[bh * HT_LD + uh], hf, HT_LD, wmma::mem_row_major);
        __syncthreads();

        // write new h (bf16) + partial MLP dot
        {
            int b = tid >> 2, q = tid & 3;
            const float* row = &Ht[b * HT_LD + q * 8];
            __nv_bfloat16 tmp[8];
            float s = 0.0f;
            #pragma unroll
            for (int u = 0; u < 8; u++) {
                float v = row[u];
                tmp[u] = __float2bfloat16(v);
                s += v * Wm[q * 8 + u];
            }
            __stcg((uint4*)&g_h[nxt][(size_t)(b0 + b) * Hh + u0 + q * 8], *(uint4*)tmp);
            s += __shfl_down_sync(0xffffffffu, s, 2, 4);
            s += __shfl_down_sync(0xffffffffu, s, 1, 4);
            if (q == 0) g_plog[((size_t)ut * Tt + t) * Bb + b0 + b] = s;
        }

        // grid barrier (monotonic counter; reset by k_init each launch)
        __threadfence();
        __syncthreads();
        if (tid == 0) {
            atomicAdd(&g_bar, 1u);
            unsigned target = (unsigned)(t + 1) * nCTA;
            while (atomicAdd(&g_bar, 0u) < target) { }
            __threadfence();
        }
        __syncthreads();
    }
}

// ---------------- reduce partial logits -> sigmoid -> out (B, T) ----------------
__global__ void k_out(const float* __restrict__ bmlp, float* __restrict__ out) {
    int t = blockIdx.x, b = threadIdx.x;
    float s = bmlp[0];
    #pragma unroll
    for (int j = 0; j < 16; j++)
        s += g_plog[((size_t)j * Tt + t) * Bb + b];
    out[(size_t)b * Tt + t] = 1.0f / (1.0f + __expf(-s));
}

// ---------------- launch ----------------
extern "C" void kernel_launch(void* const* d_in, const int* in_sizes, int n_in,
                              void* d_out, int out_size) {
    const float* x    = (const float*)d_in[0];
    const float* Wih  = (const float*)d_in[1];
    const float* Whh  = (const float*)d_in[2];
    const float* bih  = (const float*)d_in[3];
    const float* bhh  = (const float*)d_in[4];
    const float* Wmlp = (const float*)d_in[5];
    const float* bmlp = (const float*)d_in[6];
    float* out = (float*)d_out;

    k_init<<<512, 256>>>();
    k_convert<<<4096, 256>>>(Wih, Whh, bih, bhh);
    k_transpose<<<dim3(Tt / 32, Dd / 32, Bb), dim3(32, 8)>>>(x);
    k_gemm1<<<dim3(Mm / 64, G4 / 64), 128>>>();

    cudaFuncSetAttribute(k_lstm, cudaFuncAttributeMaxDynamicSharedMemorySize, DSMEM_BYTES);
    k_lstm<<<128, 128, DSMEM_BYTES>>>(Wmlp);

    k_out<<<Tt, Bb>>>(bmlp, out);
}

// round 3
// speedup vs baseline: 1.0932x; 1.0932x over previous
#include <cuda_runtime.h>
#include <cuda_bf16.h>
#include <mma.h>

using namespace nvcuda;

#define Bb 256
#define Dd 256
#define Tt 512
#define Hh 512
#define G4 2048
#define Mm (Tt*Bb)   // 131072

// ---------------- device scratch (no runtime allocation allowed) ----------------
__device__ __nv_bfloat16 g_xb[(size_t)Mm*Dd];        // xs as bf16, [t*B+b][d]
__device__ float         g_xg[(size_t)Mm*G4];        // x_gates fp32 (includes biases)
__device__ __nv_bfloat16 g_wih[(size_t)Dd*G4];       // W_ih^T bf16 [k][n]
__device__ __nv_bfloat16 g_whh[(size_t)Hh*G4];       // W_hh^T bf16 [k][n]
__device__ float         g_biasmat[16*G4];           // 16 identical rows of (b_ih+b_hh)
__device__ __nv_bfloat16 g_h[2][(size_t)Bb*Hh];      // double-buffered hidden state
__device__ float         g_plog[16*(size_t)Tt*Bb];   // partial logits per u-tile
__device__ unsigned int  g_ctr[8][32];               // per batch-group arrival counter (128B apart)

__device__ __forceinline__ float sigm(float x) { return 1.0f / (1.0f + __expf(-x)); }

// ---------------- init: zero h0 and counters ----------------
__global__ void k_init() {
    int i = blockIdx.x * blockDim.x + threadIdx.x;
    if (i < 8 * 32) ((unsigned*)g_ctr)[i] = 0u;
    if (i < Bb * Hh) g_h[0][i] = __float2bfloat16(0.0f);
}

// ---------------- weight converts (transpose to [k][n], bf16) ----------------
__global__ void k_convert(const float* __restrict__ Wih, const float* __restrict__ Whh,
                          const float* __restrict__ bih, const float* __restrict__ bhh) {
    int i = blockIdx.x * blockDim.x + threadIdx.x;
    if (i < Dd * G4) {
        int k = i / G4, n = i % G4;
        g_wih[i] = __float2bfloat16(Wih[(size_t)n * Dd + k]);
    }
    if (i < Hh * G4) {
        int k = i / G4, n = i % G4;
        g_whh[i] = __float2bfloat16(Whh[(size_t)n * Hh + k]);
    }
    if (i < 16 * G4) {
        int n = i % G4;
        g_biasmat[i] = bih[n] + bhh[n];
    }
}

// ---------------- transpose x (B,D,T) -> g_xb[(t*B+b)*D + d] bf16 ----------------
__global__ void k_transpose(const float* __restrict__ x) {
    __shared__ float tile[32][33];
    int b  = blockIdx.z;
    int d0 = blockIdx.y * 32, t0 = blockIdx.x * 32;
    int tx = threadIdx.x, ty = threadIdx.y;   // 32 x 8
    const float* src = x + ((size_t)b * Dd + d0) * Tt + t0;
    for (int r = ty; r < 32; r += 8)
        tile[r][tx] = src[(size_t)r * Tt + tx];
    __syncthreads();
    for (int r = ty; r < 32; r += 8)
        g_xb[((size_t)(t0 + r) * Bb + b) * Dd + d0 + tx] = __float2bfloat16(tile[tx][r]);
}

// ---------------- GEMM1: g_xg = g_xb (M x 256) @ g_wih (256 x 2048) + bias ----------------
// 128x128 tile, 256 threads (8 warps as 4M x 2N, each warp 32x64 = 2x4 frags)
__global__ void __launch_bounds__(256) k_gemm1() {
    __shared__ __nv_bfloat16 As[128][72];   // 144B row stride -> 16B shift per row, conflict-free
    __shared__ __nv_bfloat16 Bs[64][136];   // 272B row stride -> 16B shift per row, conflict-free
    int m0 = blockIdx.x * 128, n0 = blockIdx.y * 128;
    int tid = threadIdx.x;
    int w = tid >> 5;
    int mw = (w >> 1) * 32, nw = (w & 1) * 64;

    wmma::fragment<wmma::accumulator, 16, 16, 16, float> acc[2][4];
    #pragma unroll
    for (int i = 0; i < 2; i++)
        #pragma unroll
        for (int j = 0; j < 4; j++)
            wmma::load_matrix_sync(acc[i][j], &g_biasmat[n0 + nw + 16 * j], G4, wmma::mem_row_major);

    for (int k0 = 0; k0 < Dd; k0 += 64) {
        __syncthreads();
        #pragma unroll
        for (int p = 0; p < 4; p++) {
            int idx = tid + p * 256;
            int r = idx >> 3, c = (idx & 7) * 8;
            *(uint4*)&As[r][c] = *(const uint4*)&g_xb[(size_t)(m0 + r) * Dd + k0 + c];
        }
        #pragma unroll
        for (int p = 0; p < 4; p++) {
            int idx = tid + p * 256;
            int r = idx >> 4, c = (idx & 15) * 8;
            *(uint4*)&Bs[r][c] = *(const uint4*)&g_wih[(size_t)(k0 + r) * G4 + n0 + c];
        }
        __syncthreads();
        #pragma unroll
        for (int kk = 0; kk < 64; kk += 16) {
            wmma::fragment<wmma::matrix_a, 16, 16, 16, __nv_bfloat16, wmma::row_major> af[2];
            wmma::fragment<wmma::matrix_b, 16, 16, 16, __nv_bfloat16, wmma::row_major> bf[4];
            #pragma unroll
            for (int i = 0; i < 2; i++)
                wmma::load_matrix_sync(af[i], &As[mw + 16 * i][kk], 72);
            #pragma unroll
            for (int j = 0; j < 4; j++)
                wmma::load_matrix_sync(bf[j], &Bs[kk][nw + 16 * j], 136);
            #pragma unroll
            for (int i = 0; i < 2; i++)
                #pragma unroll
                for (int j = 0; j < 4; j++)
                    wmma::mma_sync(acc[i][j], af[i], bf[j], acc[i][j]);
        }
    }
    #pragma unroll
    for (int i = 0; i < 2; i++)
        #pragma unroll
        for (int j = 0; j < 4; j++)
            wmma::store_matrix_sync(&g_xg[(size_t)(m0 + mw + 16 * i) * G4 + n0 + nw + 16 * j],
                                    acc[i][j], G4, wmma::mem_row_major);
}

// ---------------- persistent LSTM recurrence ----------------
// grid = 128 CTAs: blockIdx = bt*16 + ut ; CTA owns batch rows [bt*32, +32), units [ut*32, +32)
// Sync: per batch-group counter; arrivals via red.release, poll via ld.acquire (one thread/CTA).
#define BS_LD 136
#define AS_LD 520
#define HT_LD 36
#define DSMEM_BYTES (512*BS_LD*2 + 32*AS_LD*2 + 32*HT_LD*4)

__global__ void __launch_bounds__(128, 1) k_lstm(const float* __restrict__ Wmlp) {
    extern __shared__ char smem[];
    __nv_bfloat16* Bs = (__nv_bfloat16*)smem;                          // [512][BS_LD]
    __nv_bfloat16* As = (__nv_bfloat16*)(smem + 512 * BS_LD * 2);      // [32][AS_LD]
    float*         Ht = (float*)(smem + 512 * BS_LD * 2 + 32 * AS_LD * 2); // [32][HT_LD]
    __shared__ float Wm[32];

    int tid = threadIdx.x, w = tid >> 5;
    int ut = blockIdx.x & 15, bt = blockIdx.x >> 4;
    int u0 = ut * 32, b0 = bt * 32;
    int bh = (w >> 1) * 16, uh = (w & 1) * 16;
    unsigned* ctr = &g_ctr[bt][0];

    // preload W_hh slice into SMEM: Bs[k][g*32+uu] = W_hh[g*512+u0+uu][k]
    for (int idx = tid; idx < 512 * 16; idx += 128) {
        int k = idx >> 4;
        int col = (idx & 15) * 8;
        int g = col >> 5, uu = col & 31;
        *(uint4*)&Bs[k * BS_LD + col] = *(const uint4*)&g_whh[(size_t)k * G4 + g * 512 + u0 + uu];
    }
    if (tid < 32) Wm[tid] = Wmlp[u0 + tid];

    float c_reg[8];
    #pragma unroll
    for (int e = 0; e < 8; e++) c_reg[e] = 0.0f;

    __syncthreads();

    for (int t = 0; t < Tt; t++) {
        int cur = t & 1, nxt = cur ^ 1;

        // copy my h rows (32 x 512 bf16) from global (L2-coherent) into SMEM
        const __nv_bfloat16* hsrc = g_h[cur] + (size_t)b0 * Hh;
        for (int idx = tid; idx < 32 * 64; idx += 128) {
            int r = idx >> 6, c = (idx & 63) * 8;
            *(uint4*)&As[r * AS_LD + c] = __ldcg((const uint4*)&hsrc[(size_t)r * Hh + c]);
        }
        __syncthreads();

        // accumulators = x_gates tile (fp32, already includes biases)
        wmma::fragment<wmma::accumulator, 16, 16, 16, float> acc[4];
        const float* xgp = g_xg + ((size_t)t * Bb + b0 + bh) * G4 + u0 + uh;
        #pragma unroll
        for (int g = 0; g < 4; g++)
            wmma::load_matrix_sync(acc[g], xgp + g * 512, G4, wmma::mem_row_major);

        // gates += h @ W_hh^T  (K = 512)
        for (int k0 = 0; k0 < 512; k0 += 16) {
            wmma::fragment<wmma::matrix_a, 16, 16, 16, __nv_bfloat16, wmma::row_major> af;
            wmma::load_matrix_sync(af, &As[bh * AS_LD + k0], AS_LD);
            #pragma unroll
            for (int g = 0; g < 4; g++) {
                wmma::fragment<wmma::matrix_b, 16, 16, 16, __nv_bfloat16, wmma::row_major> bf;
                wmma::load_matrix_sync(bf, &Bs[k0 * BS_LD + g * 32 + uh], BS_LD);
                wmma::mma_sync(acc[g], af, bf, acc[g]);
            }
        }

        // elementwise LSTM cell (c stays in registers; all 4 frags share the same layout)
        wmma::fragment<wmma::accumulator, 16, 16, 16, float> hf;
        #pragma unroll
        for (int e = 0; e < 8; e++) {
            float ig = sigm(acc[0].x[e]);
            float fg = sigm(acc[1].x[e]);
            float gg = tanhf(acc[2].x[e]);
            float og = sigm(acc[3].x[e]);
            float cn = fg * c_reg[e] + ig * gg;
            c_reg[e] = cn;
            hf.x[e] = og * tanhf(cn);
        }
        wmma::store_matrix_sync(&Ht[bh * HT_LD + uh], hf, HT_LD, wmma::mem_row_major);
        __syncthreads();

        // write new h (bf16) + partial MLP dot
        {
            int b = tid >> 2, q = tid & 3;
            const float* row = &Ht[b * HT_LD + q * 8];
            __nv_bfloat16 tmp[8];
            float s = 0.0f;
            #pragma unroll
            for (int u = 0; u < 8; u++) {
                float v = row[u];
                tmp[u] = __float2bfloat16(v);
                s += v * Wm[q * 8 + u];
            }
            __stcg((uint4*)&g_h[nxt][(size_t)(b0 + b) * Hh + u0 + q * 8], *(uint4*)tmp);
            s += __shfl_down_sync(0xffffffffu, s, 2, 4);
            s += __shfl_down_sync(0xffffffffu, s, 1, 4);
            if (q == 0) g_plog[((size_t)ut * Tt + t) * Bb + b0 + b] = s;
        }

        // group barrier: 16 CTAs of this batch group (skip after last step)
        if (t + 1 < Tt) {
            __syncthreads();   // all h-stores of this CTA issued before the release below
            if (tid == 0) {
                asm volatile("red.release.gpu.global.add.u32 [%0], 1;" :: "l"(ctr) : "memory");
                unsigned tgt = 16u * (unsigned)(t + 1);
                unsigned v;
                do {
                    asm volatile("ld.acquire.gpu.global.u32 %0, [%1];" : "=r"(v) : "l"(ctr) : "memory");
                } while (v < tgt);
            }
            __syncthreads();
        }
    }
}

// ---------------- reduce partial logits -> sigmoid -> out (B, T) ----------------
__global__ void k_out(const float* __restrict__ bmlp, float* __restrict__ out) {
    int t = blockIdx.x, b = threadIdx.x;
    float s = bmlp[0];
    #pragma unroll
    for (int j = 0; j < 16; j++)
        s += g_plog[((size_t)j * Tt + t) * Bb + b];
    out[(size_t)b * Tt + t] = 1.0f / (1.0f + __expf(-s));
}

// ---------------- launch ----------------
extern "C" void kernel_launch(void* const* d_in, const int* in_sizes, int n_in,
                              void* d_out, int out_size) {
    const float* x    = (const float*)d_in[0];
    const float* Wih  = (const float*)d_in[1];
    const float* Whh  = (const float*)d_in[2];
    const float* bih  = (const float*)d_in[3];
    const float* bhh  = (const float*)d_in[4];
    const float* Wmlp = (const float*)d_in[5];
    const float* bmlp = (const float*)d_in[6];
    float* out = (float*)d_out;

    k_init<<<512, 256>>>();
    k_convert<<<4096, 256>>>(Wih, Whh, bih, bhh);
    k_transpose<<<dim3(Tt / 32, Dd / 32, Bb), dim3(32, 8)>>>(x);
    k_gemm1<<<dim3(Mm / 128, G4 / 128), 256>>>();

    cudaFuncSetAttribute(k_lstm, cudaFuncAttributeMaxDynamicSharedMemorySize, DSMEM_BYTES);
    k_lstm<<<128, 128, DSMEM_BYTES>>>(Wmlp);

    k_out<<<Tt, Bb>>>(bmlp, out);
}